// round 16
// baseline (speedup 1.0000x reference)
#include <cuda_runtime.h>
#include <cuda_fp16.h>

// Problem constants
#define BATCH    128
#define SEQT     256
#define HID      128
#define WIN      16
#define NSTEP    3840          // (256-16)*16 chained LSTM steps
#define NTHREADS 256           // 8 warps; warp w owns gate rows [64w, 64w+64)
#define NCTA     64            // each CTA runs TWO batch chains

// Named barriers (1: sg ready -> combine; 2: h ready -> everyone)
#define BAR_ARRIVE(id) asm volatile("bar.arrive %0, %1;" :: "r"(id), "r"(NTHREADS) : "memory")
#define BAR_SYNC(id)   asm volatile("bar.sync %0, %1;"   :: "r"(id), "r"(NTHREADS) : "memory")

// HW tanh (MUFU.TANH) and sigmoid via tanh
__device__ __forceinline__ float tanh_fast(float x) {
    float y; asm("tanh.approx.f32 %0, %1;" : "=f"(y) : "f"(x)); return y;
}
__device__ __forceinline__ float sigm_fast(float x) {
    return __fmaf_rn(0.5f, tanh_fast(0.5f * x), 0.5f);
}
__device__ __forceinline__ unsigned pack_h2(float lo, float hi) {
    __half2 h = __floats2half2_rn(lo, hi);
    return *reinterpret_cast<unsigned*>(&h);
}
// m16n8k16 row.col f16*f16 -> f32 accumulate (warp-level HMMA)
__device__ __forceinline__ void mma16816(float* c, const unsigned* a, unsigned b0, unsigned b1) {
    asm volatile(
        "mma.sync.aligned.m16n8k16.row.col.f32.f16.f16.f32 "
        "{%0,%1,%2,%3},{%4,%5,%6,%7},{%8,%9},{%0,%1,%2,%3};\n"
        : "+f"(c[0]), "+f"(c[1]), "+f"(c[2]), "+f"(c[3])
        : "r"(a[0]), "r"(a[1]), "r"(a[2]), "r"(a[3]), "r"(b0), "r"(b1));
}

__global__ void __launch_bounds__(NTHREADS, 1)
lstm_dual2_kernel(const float* __restrict__ x,
                  const float* __restrict__ W_ih,
                  const float* __restrict__ W_hh,
                  const float* __restrict__ b_ih,
                  const float* __restrict__ b_hh,
                  const float* __restrict__ fc_W,
                  const float* __restrict__ fc_b,
                  float* __restrict__ out)
{
    __shared__ float sx[2 * SEQT];                 // x rows for chains A, B
    // Permuted raw gates, chain A at [0,512), chain B at [512,1024)
    __shared__ __align__(16) float sg[2 * 4 * HID];
    // h buffers, fragment-ordered: [0]=hiA [1]=loA [2]=hiB [3]=loB (256 B each)
    __shared__ __align__(16) unsigned shB4[4][64];
    __shared__ float stap[2][HID];                 // fc tap partials per chain

    const int tid = threadIdx.x;
    const int bA  = 2 * blockIdx.x;                // chain A batch row
    const int bB  = bA + 1;                        // chain B batch row
    const int w   = tid >> 5;          // warp 0..7
    const int l   = tid & 31;
    const int gid = l >> 2;            // 0..7  (frag row group / B column)
    const int tg  = l & 3;             // 0..3
    const bool combiner = (w >= 4);    // warps 4-7 run the cell combine
    const int  cu = tid - 128;         // combiner's hidden unit (0..127)

    // ---------------- Prologue: A fragments (W_hh fp16, resident in RF) ----
    // Warp w owns 4 tiles: gate rows R..R+15, R = 64w + 16t, t = 0..3.
    unsigned Afrag[4][8][4];
#pragma unroll
    for (int t = 0; t < 4; ++t) {
        const int R = 64 * w + 16 * t;
        const float* r0 = W_hh + (R + gid)     * HID;
        const float* r8 = W_hh + (R + gid + 8) * HID;
#pragma unroll
        for (int kk = 0; kk < 8; ++kk) {
            const int k0 = 16 * kk + 2 * tg;
            Afrag[t][kk][0] = pack_h2(r0[k0],     r0[k0 + 1]);
            Afrag[t][kk][1] = pack_h2(r8[k0],     r8[k0 + 1]);
            Afrag[t][kk][2] = pack_h2(r0[k0 + 8], r0[k0 + 9]);
            Afrag[t][kk][3] = pack_h2(r8[k0 + 8], r8[k0 + 9]);
        }
    }

    // Per-lane bias / W_ih (rows gid, gid+8 per tile) — SHARED by both chains
    float biasr[4][2], wihr[4][2];
#pragma unroll
    for (int t = 0; t < 4; ++t) {
        const int R = 64 * w + 16 * t;
        biasr[t][0] = b_ih[R + gid]     + b_hh[R + gid];
        biasr[t][1] = b_ih[R + gid + 8] + b_hh[R + gid + 8];
        wihr[t][0]  = W_ih[R + gid];
        wihr[t][1]  = W_ih[R + gid + 8];
    }

    const float fcw = combiner ? fc_W[cu] : 0.f;
    const float fcb = fc_b[0];
    float csA = 0.f, csB = 0.f;        // cell states (combiners, unit cu)

    if (tid < 64) { shB4[0][tid] = 0u; shB4[1][tid] = 0u;
                    shB4[2][tid] = 0u; shB4[3][tid] = 0u; }     // h0 = 0
    sx[tid]        = x[bA * SEQT + tid];
    sx[SEQT + tid] = x[bB * SEQT + tid];
    if (tid < WIN) {
        out[bA * SEQT + tid] = sx[tid];
        out[bB * SEQT + tid] = sx[SEQT + tid];
    }
    __syncthreads();

    // Combiner's h-store byte offset in the fragment-ordered buffer:
    //   kk=cu>>4, b3=(cu>>3)&1, tg=(cu>>1)&3, e=cu&1
    const int frag_off = combiner
        ? (((cu >> 4) << 5) + (((cu >> 1) & 3) << 3) + (((cu >> 3) & 1) << 2) + ((cu & 1) << 1))
        : 0;
    char* hbase = (char*)shB4 + frag_off;   // +0 hiA, +256 loA, +512 hiB, +768 loB

    // Combiner's permuted gate-slot index: q = slot(cu); gates at q + 128*g.
    const int q = combiner
        ? ((cu & ~15) + ((cu & 7) << 1) + ((cu >> 3) & 1))
        : 0;

    // Producer's paired-store slot (float2 index): rows (R+gid, R+gid+8)
    // live at float offset 64w+16t+2gid -> float2 index 32w + 8t + gid.
    float2* sg2 = (float2*)sg;
    const int sgslot = 32 * w + gid;       // + 8*t per tile  (FIXED: gid * 1)

    // B-operand base (chain A): column gid==1 reads h_lo; others read h_hi.
    // Chain B operands live at +512 bytes.
    const char* bpc = (const char*)shB4 + ((gid == 1) ? 256 : 0);

    // ---------------- 3840 chained steps (x2 chains per iteration) ---------
    for (int s = 0; s < NSTEP; ++s) {
        const int idx = (s >> 4) + (s & (WIN - 1));
        const float xtA = sx[idx];
        const float xtB = sx[SEQT + idx];

        // cA = chain A accumulators (depth-8), cB = chain B (depth-8).
        float cA[4][4], cB[4][4];
#pragma unroll
        for (int t = 0; t < 4; ++t) {
            if (tg == 0) {
                cA[t][0] = __fmaf_rn(xtA, wihr[t][0], biasr[t][0]);
                cA[t][2] = __fmaf_rn(xtA, wihr[t][1], biasr[t][1]);
                cB[t][0] = __fmaf_rn(xtB, wihr[t][0], biasr[t][0]);
                cB[t][2] = __fmaf_rn(xtB, wihr[t][1], biasr[t][1]);
            } else {
                cA[t][0] = 0.f; cA[t][2] = 0.f;
                cB[t][0] = 0.f; cB[t][2] = 0.f;
            }
            cA[t][1] = 0.f; cA[t][3] = 0.f;
            cB[t][1] = 0.f; cB[t][3] = 0.f;
        }

        // Interleaved MMA phases: per k-step, LDS.64 for each chain + 8 MMAs.
#pragma unroll
        for (int kk = 0; kk < 8; ++kk) {
            const uint2 bbA = *(const uint2*)(bpc + kk * 32 + tg * 8);
            const uint2 bbB = *(const uint2*)(bpc + 512 + kk * 32 + tg * 8);
            mma16816(cA[0], Afrag[0][kk], bbA.x, bbA.y);
            mma16816(cB[0], Afrag[0][kk], bbB.x, bbB.y);
            mma16816(cA[1], Afrag[1][kk], bbA.x, bbA.y);
            mma16816(cB[1], Afrag[1][kk], bbB.x, bbB.y);
            mma16816(cA[2], Afrag[2][kk], bbA.x, bbA.y);
            mma16816(cB[2], Afrag[2][kk], bbB.x, bbB.y);
            mma16816(cA[3], Afrag[3][kk], bbA.x, bbA.y);
            mma16816(cB[3], Afrag[3][kk], bbB.x, bbB.y);
        }

        // tg==0 lanes: raw gate = col0 + col1; one STS.64 per tile per chain.
        if (tg == 0) {
#pragma unroll
            for (int t = 0; t < 4; ++t) {
                sg2[sgslot + 8 * t]       = make_float2(cA[t][0] + cA[t][1],
                                                        cA[t][2] + cA[t][3]);
                sg2[256 + sgslot + 8 * t] = make_float2(cB[t][0] + cB[t][1],
                                                        cB[t][2] + cB[t][3]);
            }
        }

        const bool tap = ((s & (WIN - 1)) == (WIN - 1));

        if (!combiner) {
            // Producers: post sg, then block once until h is ready.
            BAR_ARRIVE(1);
            BAR_SYNC(2);
        } else {
            // Combiners (warps 4-7): wait for sg, run BOTH cells.
            BAR_SYNC(1);

            // Chain A
            const float giA = sg[q];
            const float gfA = sg[q + HID];
            const float ggA = sg[q + 2 * HID];
            const float goA = sg[q + 3 * HID];
            csA = sigm_fast(gfA) * csA + sigm_fast(giA) * tanh_fast(ggA);
            const float hA = sigm_fast(goA) * tanh_fast(csA);
            // Chain B
            const float giB = sg[512 + q];
            const float gfB = sg[512 + q + HID];
            const float ggB = sg[512 + q + 2 * HID];
            const float goB = sg[512 + q + 3 * HID];
            csB = sigm_fast(gfB) * csB + sigm_fast(giB) * tanh_fast(ggB);
            const float hB = sigm_fast(goB) * tanh_fast(csB);

            // Truncation splits (hi exact in fp16, lo exact residual)
            const float hiA = __uint_as_float(__float_as_uint(hA) & 0xFFFFE000u);
            const float hiB = __uint_as_float(__float_as_uint(hB) & 0xFFFFE000u);
            *(__half*)(hbase)       = __float2half_rn(hiA);
            *(__half*)(hbase + 256) = __float2half_rn(hA - hiA);
            *(__half*)(hbase + 512) = __float2half_rn(hiB);
            *(__half*)(hbase + 768) = __float2half_rn(hB - hiB);

            if (tap) { stap[0][cu] = fcw * hA; stap[1][cu] = fcw * hB; }

            BAR_SYNC(2);

            // Deferred fc-tap reduces, overlapped with next-step MMA issue:
            // warp 4 -> chain A, warp 5 -> chain B.
            if (tap && (w == 4 || w == 5)) {
                const float* sp = stap[w - 4];
                float p = sp[l] + sp[l + 32] + sp[l + 64] + sp[l + 96];
                p += __shfl_down_sync(0xffffffffu, p, 16);
                p += __shfl_down_sync(0xffffffffu, p, 8);
                p += __shfl_down_sync(0xffffffffu, p, 4);
                p += __shfl_down_sync(0xffffffffu, p, 2);
                p += __shfl_down_sync(0xffffffffu, p, 1);
                if (l == 0) {
                    const float v = p + fcb;
                    const int row = (w == 4) ? bA : bB;
                    out[row * SEQT + WIN + (s >> 4)] = (v >= 0.f) ? v : 0.3f * v;
                }
            }
        }
    }
}

extern "C" void kernel_launch(void* const* d_in, const int* in_sizes, int n_in,
                              void* d_out, int out_size)
{
    const float* x    = (const float*)d_in[0];
    const float* W_ih = (const float*)d_in[1];
    const float* W_hh = (const float*)d_in[2];
    const float* b_ih = (const float*)d_in[3];
    const float* b_hh = (const float*)d_in[4];
    const float* fc_W = (const float*)d_in[5];
    const float* fc_b = (const float*)d_in[6];

    lstm_dual2_kernel<<<NCTA, NTHREADS>>>(
        x, W_ih, W_hh, b_ih, b_hh, fc_W, fc_b, (float*)d_out);
}

// round 17
// speedup vs baseline: 1.3195x; 1.3195x over previous
#include <cuda_runtime.h>
#include <cuda_fp16.h>

// Problem constants
#define BATCH    128
#define SEQT     256
#define HID      128
#define WIN      16
#define NSTEP    3840          // chained LSTM steps per batch row
#define NTHREADS 256           // 8 warps; warp w owns gate rows [64w, 64w+64)
#define NCTA     64            // each CTA runs TWO batch chains (cols 0-1 / 2-3)

// Named barriers (1: sg ready -> combine; 2: h ready -> everyone)
#define BAR_ARRIVE(id) asm volatile("bar.arrive %0, %1;" :: "r"(id), "r"(NTHREADS) : "memory")
#define BAR_SYNC(id)   asm volatile("bar.sync %0, %1;"   :: "r"(id), "r"(NTHREADS) : "memory")

// HW tanh (MUFU.TANH) and sigmoid via tanh
__device__ __forceinline__ float tanh_fast(float x) {
    float y; asm("tanh.approx.f32 %0, %1;" : "=f"(y) : "f"(x)); return y;
}
__device__ __forceinline__ float sigm_fast(float x) {
    return __fmaf_rn(0.5f, tanh_fast(0.5f * x), 0.5f);
}
__device__ __forceinline__ unsigned pack_h2(float lo, float hi) {
    __half2 h = __floats2half2_rn(lo, hi);
    return *reinterpret_cast<unsigned*>(&h);
}
// m16n8k16 row.col f16*f16 -> f32 accumulate (warp-level HMMA)
__device__ __forceinline__ void mma16816(float* c, const unsigned* a, unsigned b0, unsigned b1) {
    asm volatile(
        "mma.sync.aligned.m16n8k16.row.col.f32.f16.f16.f32 "
        "{%0,%1,%2,%3},{%4,%5,%6,%7},{%8,%9},{%0,%1,%2,%3};\n"
        : "+f"(c[0]), "+f"(c[1]), "+f"(c[2]), "+f"(c[3])
        : "r"(a[0]), "r"(a[1]), "r"(a[2]), "r"(a[3]), "r"(b0), "r"(b1));
}

__global__ void __launch_bounds__(NTHREADS, 1)
lstm_ncol_kernel(const float* __restrict__ x,
                 const float* __restrict__ W_ih,
                 const float* __restrict__ W_hh,
                 const float* __restrict__ b_ih,
                 const float* __restrict__ b_hh,
                 const float* __restrict__ fc_W,
                 const float* __restrict__ fc_b,
                 float* __restrict__ out)
{
    __shared__ float sx[2 * SEQT];                 // x rows: A at [0,256), B at [256,512)
    // Permuted raw gates: chain A at floats [0,512), chain B at [512,1024)
    __shared__ __align__(16) float sg[2 * 4 * HID];
    // h buffers, fragment-ordered, 256 B each: [0]=hiA [1]=loA [2]=hiB [3]=loB
    __shared__ __align__(16) unsigned shB4[4][64];
    __shared__ float stap[2][HID];                 // fc tap partials per chain

    const int tid = threadIdx.x;
    const int bA  = 2 * blockIdx.x;
    const int bB  = bA + 1;
    const int w   = tid >> 5;          // warp 0..7
    const int l   = tid & 31;
    const int gid = l >> 2;            // 0..7  (frag row group / B column)
    const int tg  = l & 3;             // 0..3  (tg=0 -> chain A cols, tg=1 -> chain B)
    const bool combiner = (w >= 4);    // warps 4-7 run the cell combine
    const int  cu = tid - 128;         // combiner's hidden unit (0..127)

    // ---------------- Prologue: A fragments (W_hh fp16, resident in RF) ----
    // Warp w owns 4 tiles: gate rows R..R+15, R = 64w + 16t, t = 0..3.
    unsigned Afrag[4][8][4];
#pragma unroll
    for (int t = 0; t < 4; ++t) {
        const int R = 64 * w + 16 * t;
        const float* r0 = W_hh + (R + gid)     * HID;
        const float* r8 = W_hh + (R + gid + 8) * HID;
#pragma unroll
        for (int kk = 0; kk < 8; ++kk) {
            const int k0 = 16 * kk + 2 * tg;
            Afrag[t][kk][0] = pack_h2(r0[k0],     r0[k0 + 1]);
            Afrag[t][kk][1] = pack_h2(r8[k0],     r8[k0 + 1]);
            Afrag[t][kk][2] = pack_h2(r0[k0 + 8], r0[k0 + 9]);
            Afrag[t][kk][3] = pack_h2(r8[k0 + 8], r8[k0 + 9]);
        }
    }

    // Per-lane bias / W_ih (rows gid, gid+8 per tile) — shared by both chains
    float biasr[4][2], wihr[4][2];
#pragma unroll
    for (int t = 0; t < 4; ++t) {
        const int R = 64 * w + 16 * t;
        biasr[t][0] = b_ih[R + gid]     + b_hh[R + gid];
        biasr[t][1] = b_ih[R + gid + 8] + b_hh[R + gid + 8];
        wihr[t][0]  = W_ih[R + gid];
        wihr[t][1]  = W_ih[R + gid + 8];
    }

    const float fcw = combiner ? fc_W[cu] : 0.f;
    const float fcb = fc_b[0];
    float csA = 0.f, csB = 0.f;        // cell states (combiners, unit cu)

    if (tid < 64) { shB4[0][tid] = 0u; shB4[1][tid] = 0u;
                    shB4[2][tid] = 0u; shB4[3][tid] = 0u; }     // h0 = 0
    sx[tid]        = x[bA * SEQT + tid];
    sx[SEQT + tid] = x[bB * SEQT + tid];
    if (tid < WIN) {
        out[bA * SEQT + tid] = sx[tid];
        out[bB * SEQT + tid] = sx[SEQT + tid];
    }
    __syncthreads();

    // Combiner's h-store byte offset in the fragment-ordered buffer:
    //   kk=cu>>4, b3=(cu>>3)&1, tg=(cu>>1)&3, e=cu&1
    const int frag_off = combiner
        ? (((cu >> 4) << 5) + (((cu >> 1) & 3) << 3) + (((cu >> 3) & 1) << 2) + ((cu & 1) << 1))
        : 0;
    char* hbase = (char*)shB4 + frag_off;   // +0 hiA, +256 loA, +512 hiB, +768 loB

    // Combiner's permuted gate-slot index: q = slot(cu); gates at q + 128*g.
    const int q = combiner
        ? ((cu & ~15) + ((cu & 7) << 1) + ((cu >> 3) & 1))
        : 0;

    // Producer's paired-store slot (float2 index): 32w + 8t + gid.
    float2* sg2 = (float2*)sg;
    const int sgslot = 32 * w + gid;       // + 8*t per tile

    // B-operand buffer for this lane's column n = gid:
    //   0 -> hA_hi, 1 -> hA_lo, 2 -> hB_hi, 3 -> hB_lo, 4..7 -> dummy (hA_hi)
    const int hoff = (gid == 1) ? 256 : (gid == 2) ? 512 : (gid == 3) ? 768 : 0;
    const char* bpc = (const char*)shB4 + hoff;

    // This lane's x row for the init fold (tg==0 -> chain A, tg==1 -> chain B)
    const float* xrow = (tg == 1) ? (sx + SEQT) : sx;

    // Prefetched per-step init: x*W_ih + bias (used by tg==0 / tg==1 lanes)
    float init_[4][2];
    {
        const float xt0 = xrow[0];
#pragma unroll
        for (int t = 0; t < 4; ++t) {
            init_[t][0] = __fmaf_rn(xt0, wihr[t][0], biasr[t][0]);
            init_[t][1] = __fmaf_rn(xt0, wihr[t][1], biasr[t][1]);
        }
    }

    // -------- 3840 steps, BOTH chains per iteration via N-columns ----------
    for (int s = 0; s < NSTEP; ++s) {
        // Two half-depth chains per tile: cA (kk 0..3) + cB (kk 4..7).
        // Chain A rides D cols 0-1 (tg==0 lanes), chain B cols 2-3 (tg==1).
        float cA[4][4], cB[4][4];
#pragma unroll
        for (int t = 0; t < 4; ++t) {
            if (tg < 2) { cA[t][0] = init_[t][0]; cA[t][2] = init_[t][1]; }
            else        { cA[t][0] = 0.f;         cA[t][2] = 0.f; }
            cA[t][1] = 0.f; cA[t][3] = 0.f;
            cB[t][0] = 0.f; cB[t][1] = 0.f; cB[t][2] = 0.f; cB[t][3] = 0.f;
        }

        // One LDS.64 per k-step (per lane, from its column's buffer).
#pragma unroll
        for (int kk = 0; kk < 4; ++kk) {
            const uint2 bb = *(const uint2*)(bpc + kk * 32 + tg * 8);
            mma16816(cA[0], Afrag[0][kk], bb.x, bb.y);
            mma16816(cA[1], Afrag[1][kk], bb.x, bb.y);
            mma16816(cA[2], Afrag[2][kk], bb.x, bb.y);
            mma16816(cA[3], Afrag[3][kk], bb.x, bb.y);
        }
#pragma unroll
        for (int kk = 4; kk < 8; ++kk) {
            const uint2 bb = *(const uint2*)(bpc + kk * 32 + tg * 8);
            mma16816(cB[0], Afrag[0][kk], bb.x, bb.y);
            mma16816(cB[1], Afrag[1][kk], bb.x, bb.y);
            mma16816(cB[2], Afrag[2][kk], bb.x, bb.y);
            mma16816(cB[3], Afrag[3][kk], bb.x, bb.y);
        }

        // Gate = (hi col) + (lo col): tg==0 lanes own chain A (cols 0,1),
        // tg==1 lanes own chain B (cols 2,3). One STS.64 per tile per lane.
        if (tg == 0) {
#pragma unroll
            for (int t = 0; t < 4; ++t)
                sg2[sgslot + 8 * t] = make_float2((cA[t][0] + cB[t][0]) + (cA[t][1] + cB[t][1]),
                                                  (cA[t][2] + cB[t][2]) + (cA[t][3] + cB[t][3]));
        } else if (tg == 1) {
#pragma unroll
            for (int t = 0; t < 4; ++t)
                sg2[256 + sgslot + 8 * t] = make_float2((cA[t][0] + cB[t][0]) + (cA[t][1] + cB[t][1]),
                                                        (cA[t][2] + cB[t][2]) + (cA[t][3] + cB[t][3]));
        }

        // Prefetch next step's init (h-independent) before blocking.
        {
            const int s1 = s + 1;
            const float xt1 = xrow[(s1 >> 4) + (s1 & (WIN - 1))];
#pragma unroll
            for (int t = 0; t < 4; ++t) {
                init_[t][0] = __fmaf_rn(xt1, wihr[t][0], biasr[t][0]);
                init_[t][1] = __fmaf_rn(xt1, wihr[t][1], biasr[t][1]);
            }
        }

        const bool tap = ((s & (WIN - 1)) == (WIN - 1));

        if (!combiner) {
            BAR_ARRIVE(1);
            BAR_SYNC(2);
        } else {
            BAR_SYNC(1);

            // Chain A cell
            const float giA = sg[q];
            const float gfA = sg[q + HID];
            const float ggA = sg[q + 2 * HID];
            const float goA = sg[q + 3 * HID];
            csA = sigm_fast(gfA) * csA + sigm_fast(giA) * tanh_fast(ggA);
            const float hA = sigm_fast(goA) * tanh_fast(csA);
            // Chain B cell
            const float giB = sg[512 + q];
            const float gfB = sg[512 + q + HID];
            const float ggB = sg[512 + q + 2 * HID];
            const float goB = sg[512 + q + 3 * HID];
            csB = sigm_fast(gfB) * csB + sigm_fast(giB) * tanh_fast(ggB);
            const float hB = sigm_fast(goB) * tanh_fast(csB);

            // Truncation splits (hi exact in fp16, lo exact residual)
            const float hiA = __uint_as_float(__float_as_uint(hA) & 0xFFFFE000u);
            const float hiB = __uint_as_float(__float_as_uint(hB) & 0xFFFFE000u);
            *(__half*)(hbase)       = __float2half_rn(hiA);
            *(__half*)(hbase + 256) = __float2half_rn(hA - hiA);
            *(__half*)(hbase + 512) = __float2half_rn(hiB);
            *(__half*)(hbase + 768) = __float2half_rn(hB - hiB);

            if (tap) { stap[0][cu] = fcw * hA; stap[1][cu] = fcw * hB; }

            BAR_SYNC(2);

            // Deferred fc-tap reduces, overlapped with next-step MMA issue:
            // warp 4 -> chain A, warp 5 -> chain B.
            if (tap && (w == 4 || w == 5)) {
                const float* sp = stap[w - 4];
                float p = sp[l] + sp[l + 32] + sp[l + 64] + sp[l + 96];
                p += __shfl_down_sync(0xffffffffu, p, 16);
                p += __shfl_down_sync(0xffffffffu, p, 8);
                p += __shfl_down_sync(0xffffffffu, p, 4);
                p += __shfl_down_sync(0xffffffffu, p, 2);
                p += __shfl_down_sync(0xffffffffu, p, 1);
                if (l == 0) {
                    const float v = p + fcb;
                    const int row = (w == 4) ? bA : bB;
                    out[row * SEQT + WIN + (s >> 4)] = (v >= 0.f) ? v : 0.3f * v;
                }
            }
        }
    }
}

extern "C" void kernel_launch(void* const* d_in, const int* in_sizes, int n_in,
                              void* d_out, int out_size)
{
    const float* x    = (const float*)d_in[0];
    const float* W_ih = (const float*)d_in[1];
    const float* W_hh = (const float*)d_in[2];
    const float* b_ih = (const float*)d_in[3];
    const float* b_hh = (const float*)d_in[4];
    const float* fc_W = (const float*)d_in[5];
    const float* fc_b = (const float*)d_in[6];

    lstm_ncol_kernel<<<NCTA, NTHREADS>>>(
        x, W_ih, W_hh, b_ih, b_hh, fc_W, fc_b, (float*)d_out);
}